// round 8
// baseline (speedup 1.0000x reference)
#include <cuda_runtime.h>
#include <math_constants.h>

#define HH   512
#define NH   32
#define LL   8192
#define NCHUNK 8            // per h-row: 8 chunks, each covers 1024 l-values
#define TSTEPS 32           // l-steps per lane (stride 32) per chunk
#define WIN  16             // steps per combine window

// Per-(h,n) constant table, 6 float2 slots: [h][slot][n]
//   0 : w^1024   1 : w^2048   2 : w^4096   3 : w^-32   4 : C2   5 : (T, -Q)
#define SLOTS 6
__device__ float2 g_tab[HH * SLOTS * NH];
// Lane-power table: g_pw4[h][j][lane] = (w_{2j}^lane, w_{2j+1}^lane)
__device__ float4 g_pw4[HH * 16 * NH];

// ---------------- f32x2 packed helpers ----------------
static __device__ __forceinline__ unsigned long long pk2(float lo, float hi) {
    unsigned long long r;
    asm("mov.b64 %0, {%1, %2};" : "=l"(r) : "f"(lo), "f"(hi));
    return r;
}
static __device__ __forceinline__ void upk2(unsigned long long v, float& lo, float& hi) {
    asm("mov.b64 {%0, %1}, %2;" : "=f"(lo), "=f"(hi) : "l"(v));
}
static __device__ __forceinline__ unsigned long long mul2(unsigned long long a, unsigned long long b) {
    unsigned long long d;
    asm("mul.rn.f32x2 %0, %1, %2;" : "=l"(d) : "l"(a), "l"(b));
    return d;
}
static __device__ __forceinline__ unsigned long long add2(unsigned long long a, unsigned long long b) {
    unsigned long long d;
    asm("add.rn.f32x2 %0, %1, %2;" : "=l"(d) : "l"(a), "l"(b));
    return d;
}
static __device__ __forceinline__ unsigned long long fma2(unsigned long long a, unsigned long long b,
                                                          unsigned long long c) {
    unsigned long long d;
    asm("fma.rn.f32x2 %0, %1, %2, %3;" : "=l"(d) : "l"(a), "l"(b), "l"(c));
    return d;
}
static __device__ __forceinline__ float2 cmulf(float2 a, float2 b) {
    float2 r;
    r.x = fmaf(a.x, b.x, -(a.y * b.y));
    r.y = fmaf(a.x, b.y,  (a.y * b.x));
    return r;
}

// w^p for large p without fp64 transcendentals
static __device__ __forceinline__ float2 bigpow(float dtar, float dtai, float p) {
    double u = (double)dtai * (double)p * (1.0 / CUDART_PI);
    double f = u - 2.0 * rint(u * 0.5);          // in [-1, 1]
    float s, c;
    sincospif((float)f, &s, &c);
    float mag = expf(dtar * p);                  // underflow to 0 == true answer
    return make_float2(mag * c, mag * s);
}

// ---------------- Fused setup: constants + lane-power table ----------------
__global__ void __launch_bounds__(512) s4d_setup(const float* __restrict__ Cr,
                                                 const float* __restrict__ Ci,
                                                 const float* __restrict__ ldt,
                                                 const float* __restrict__ lar,
                                                 const float* __restrict__ Aim) {
    __shared__ float2 lev[5][NH];     // w^(2^k), k=0..4

    int h = blockIdx.x;
    int t = threadIdx.x;

    if (t < NH) {
        int n = t;
        int idx = h * NH + n;

        float dtf  = expf(ldt[h]);
        float arf  = -expf(lar[idx]);
        float aif  = Aim[idx];
        float dtar = arf * dtf;
        float dtai = aif * dtf;

        float er, si, co;
        er = expf(dtar);
        sincosf(dtai, &si, &co);
        float2 w = make_float2(er * co, er * si);

        float nr = w.x - 1.0f, ni = w.y;
        float den = arf * arf + aif * aif;
        float inv = 1.0f / den;
        float fr = (nr * arf + ni * aif) * inv;
        float fi = (ni * arf - nr * aif) * inv;
        float cr = Cr[idx], ci = Ci[idx];
        float2 C2 = make_float2(2.0f * (cr * fr - ci * fi),
                                2.0f * (cr * fi + ci * fr));

        float2 x = w;
        #pragma unroll
        for (int k = 0; k < 5; ++k) {
            lev[k][n] = x;
            float tr = fmaf(x.x, x.x, -(x.y * x.y));
            x.y = 2.0f * x.x * x.y;
            x.x = tr;
        }
        float2 w32 = x;

        float2* dst = g_tab + (h * SLOTS) * NH + n;
        dst[0 * NH] = bigpow(dtar, dtai, 1024.0f);
        dst[1 * NH] = bigpow(dtar, dtai, 2048.0f);
        dst[2 * NH] = bigpow(dtar, dtai, 4096.0f);
        float q  = fmaf(w32.x, w32.x, w32.y * w32.y);
        float qi = 1.0f / q;
        dst[3 * NH] = make_float2(w32.x * qi, -w32.y * qi);   // w^-32
        dst[4 * NH] = C2;
        dst[5 * NH] = make_float2(2.0f * w32.x, -q);          // (T, -Q)
    }
    __syncthreads();

    int l = t >> 4;          // 0..31
    int j = t & 15;          // mode pair
    int m0 = 2 * j, m1 = 2 * j + 1;
    float2 a = make_float2(1.0f, 0.0f);
    float2 b = make_float2(1.0f, 0.0f);
    #pragma unroll
    for (int k = 0; k < 5; ++k) {
        if ((l >> k) & 1) {
            a = cmulf(a, lev[k][m0]);
            b = cmulf(b, lev[k][m1]);
        }
    }
    g_pw4[(h * 16 + j) * NH + l] = make_float4(a.x, a.y, b.x, b.y);
}

// ---------------- Main ----------------
// Block = 128 threads (4 warps). Block handles (h, cpair): chunks cpair*2 + {0,1}
// of 8. Warp w: local chunk p = w>>1, mode-half halfm = w&1.
// Per step each warp emits a 32-lane partial into sBuf; every WIN steps the two
// warps of a chunk combine (named barrier, 64 threads) and store float4.
__global__ void __launch_bounds__(128, 4) s4d_main(float* __restrict__ out) {
    __shared__ float2 sC[2][NH];        // C2 * J(chunk)
    __shared__ float2 sD[2][NH];        // C2 * J * w^-32
    __shared__ float2 sT[NH];           // (T, -Q)  (chunk-independent)
    __shared__ float  sBuf[4][WIN * 32];

    int h     = blockIdx.x >> 2;
    int cpair = blockIdx.x & 3;
    int tid   = threadIdx.x;
    int wid   = tid >> 5;
    int lane  = tid & 31;
    int p     = wid >> 1;               // local chunk 0/1
    int halfm = wid & 1;                // mode half
    int c     = cpair * 2 + p;          // global chunk 0..7

    // Phase 1: half-0 warps build per-chunk constants; warp 0 builds sT.
    if (halfm == 0) {
        const float2* gt = g_tab + (h * SLOTS) * NH + lane;
        float2 C2   = gt[4 * NH];
        float2 J = make_float2(1.0f, 0.0f);
        if (c & 1) J = gt[0 * NH];
        if (c & 2) J = cmulf(J, gt[1 * NH]);
        if (c & 4) J = cmulf(J, gt[2 * NH]);
        float2 C2J = cmulf(C2, J);
        sC[p][lane] = C2J;
        sD[p][lane] = cmulf(C2J, gt[3 * NH]);
        if (wid == 0) sT[lane] = gt[5 * NH];
    }
    __syncthreads();

    // Phase 2: per-thread init, 8 mode-pairs
    unsigned long long cur[8], prv[8], T2[8], Qn[8];
    {
        const float4* pw = g_pw4 + (h * 16 + halfm * 8) * NH + lane;
        #pragma unroll
        for (int j = 0; j < 8; ++j) {
            int jj = halfm * 8 + j;
            int m0 = 2 * jj, m1 = 2 * jj + 1;
            float4 v = pw[j * NH];                   // coalesced across lanes
            float2 wl0 = make_float2(v.x, v.y);
            float2 wl1 = make_float2(v.z, v.w);
            float2 pa = cmulf(wl0, sC[p][m0]);
            float2 pb = cmulf(wl1, sC[p][m1]);
            float2 qa = cmulf(wl0, sD[p][m0]);
            float2 qb = cmulf(wl1, sD[p][m1]);
            cur[j] = pk2(pa.x, pb.x);
            prv[j] = pk2(qa.x, qb.x);
            T2[j]  = pk2(sT[m0].x, sT[m1].x);        //  T  = 2 Re(w^32)
            Qn[j]  = pk2(sT[m0].y, sT[m1].y);        // -Q  = -|w^32|^2
        }
    }

    // chunk c covers l in [c*1024, (c+1)*1024); this block's base:
    float* opc = out + h * LL + cpair * 2 * (LL / NCHUNK);
    int barid = p + 1;                  // named barrier per chunk group

    #pragma unroll 1
    for (int win = 0; win < TSTEPS / WIN; ++win) {
        // ---- WIN steps, partials to smem ----
        #pragma unroll
        for (int s = 0; s < WIN; s += 2) {
            {
                unsigned long long s4[4];
                #pragma unroll
                for (int j = 0; j < 4; ++j) s4[j] = add2(cur[2 * j], cur[2 * j + 1]);
                unsigned long long acc = add2(add2(s4[0], s4[1]), add2(s4[2], s4[3]));
                float lo, hi;
                upk2(acc, lo, hi);
                sBuf[wid][s * 32 + lane] = lo + hi;
            }
            #pragma unroll
            for (int j = 0; j < 8; ++j)
                prv[j] = fma2(T2[j], cur[j], mul2(Qn[j], prv[j]));

            {
                unsigned long long s4[4];
                #pragma unroll
                for (int j = 0; j < 4; ++j) s4[j] = add2(prv[2 * j], prv[2 * j + 1]);
                unsigned long long acc = add2(add2(s4[0], s4[1]), add2(s4[2], s4[3]));
                float lo, hi;
                upk2(acc, lo, hi);
                sBuf[wid][(s + 1) * 32 + lane] = lo + hi;
            }
            #pragma unroll
            for (int j = 0; j < 8; ++j)
                cur[j] = fma2(T2[j], prv[j], mul2(Qn[j], cur[j]));
        }
        asm volatile("bar.sync %0, %1;" :: "r"(barid), "r"(64) : "memory");

        // ---- combine halves + coalesced store (2 warps of this chunk only) ----
        {
            int t64 = tid & 63;
            const float4* b0 = (const float4*)sBuf[2 * p];
            const float4* b1 = (const float4*)sBuf[2 * p + 1];
            float* dst = opc + p * (LL / NCHUNK) + win * (WIN * 32);
            #pragma unroll
            for (int it = 0; it < (WIN * 32) / (64 * 4); ++it) {
                int i = it * 64 + t64;              // float4 index
                float4 x = b0[i];
                float4 y = b1[i];
                float4 r = make_float4(x.x + y.x, x.y + y.y, x.z + y.z, x.w + y.w);
                __stcs((float4*)(dst + i * 4), r);
            }
        }
        asm volatile("bar.sync %0, %1;" :: "r"(barid), "r"(64) : "memory");
    }
}

extern "C" void kernel_launch(void* const* d_in, const int* in_sizes, int n_in,
                              void* d_out, int out_size) {
    const float* C_real     = (const float*)d_in[0];
    const float* C_imag     = (const float*)d_in[1];
    const float* log_dt     = (const float*)d_in[2];
    const float* log_a_real = (const float*)d_in[3];
    const float* A_imag     = (const float*)d_in[4];
    float* out = (float*)d_out;

    s4d_setup<<<HH, 512>>>(C_real, C_imag, log_dt, log_a_real, A_imag);
    s4d_main<<<HH * (NCHUNK / 2), 128>>>(out);
}

// round 10
// speedup vs baseline: 1.0894x; 1.0894x over previous
#include <cuda_runtime.h>
#include <cuda_bf16.h>
#include <math_constants.h>
#include <cstdint>

#define HH 512
#define NH 32
#define LL 8192

// l = 32a + b.  K[h, 32a+b] = sum_n MR[a,n]*VR[n,b] - MI[a,n]*VI[n,b]
// Real GEMM per h: A[256 x 64] (k=2n -> MR, k=2n+1 -> MI) times B[64 x 32]
// (k=2n -> VR, k=2n+1 -> -VI).  M[a,n] = C2_n * w_n^(32a),  V[n,b] = w_n^b.

// Tables built by setup
__device__ float2 g_V  [HH * NH * NH];   // [h][b][n] = (VR, -VI)
__device__ float2 g_TWr[HH * NH * NH];   // [h][r][n] = w^(32 r)
__device__ float2 g_Mq [HH * 8  * NH];   // [h][q][n] = C2 * w^(1024 q)
__device__ float4 g_aux[HH * NH];        // (dtar, dtai, C2.x, C2.y)

// ---------------- helpers ----------------
static __device__ __forceinline__ float2 cmulf(float2 a, float2 b) {
    float2 r;
    r.x = fmaf(a.x, b.x, -(a.y * b.y));
    r.y = fmaf(a.x, b.y,  (a.y * b.x));
    return r;
}
static __device__ __forceinline__ float2 bigpow(float dtar, float dtai, float p) {
    double u = (double)dtai * (double)p * (1.0 / CUDART_PI);
    double f = u - 2.0 * rint(u * 0.5);          // in [-1, 1]
    float s, c;
    sincospif((float)f, &s, &c);
    float mag = expf(dtar * p);                  // underflow to 0 == true answer
    return make_float2(mag * c, mag * s);
}
// pack complex (re, im) -> bf16x2 (re in low half) + residual pack
static __device__ __forceinline__ void bfsplit(float re, float im,
                                               uint32_t& p0, uint32_t& p1) {
    __nv_bfloat162 h0 = __float22bfloat162_rn(make_float2(re, im));
    float2 f0 = __bfloat1622float2(h0);
    __nv_bfloat162 h1 = __float22bfloat162_rn(make_float2(re - f0.x, im - f0.y));
    p0 = *reinterpret_cast<uint32_t*>(&h0);
    p1 = *reinterpret_cast<uint32_t*>(&h1);
}
static __device__ __forceinline__ void mma_bf16(float& c0, float& c1, float& c2, float& c3,
                                                uint32_t a0, uint32_t a1, uint32_t a2, uint32_t a3,
                                                uint32_t b0, uint32_t b1) {
    asm volatile(
        "mma.sync.aligned.m16n8k16.row.col.f32.bf16.bf16.f32 "
        "{%0,%1,%2,%3}, {%4,%5,%6,%7}, {%8,%9}, {%0,%1,%2,%3};"
        : "+f"(c0), "+f"(c1), "+f"(c2), "+f"(c3)
        : "r"(a0), "r"(a1), "r"(a2), "r"(a3), "r"(b0), "r"(b1));
}

// ---------------- Setup 1: per-(h,n) chains ----------------
__global__ void __launch_bounds__(256) s4d_setup1(const float* __restrict__ Cr,
                                                  const float* __restrict__ Ci,
                                                  const float* __restrict__ ldt,
                                                  const float* __restrict__ lar,
                                                  const float* __restrict__ Aim) {
    int t = threadIdx.x;
    int h = blockIdx.x * 8 + (t >> 5);
    int n = t & 31;
    int idx = h * NH + n;

    float dtf  = expf(ldt[h]);
    float arf  = -expf(lar[idx]);
    float aif  = Aim[idx];
    float dtar = arf * dtf;
    float dtai = aif * dtf;

    float er, si, co;
    er = expf(dtar);
    sincosf(dtai, &si, &co);
    float2 w = make_float2(er * co, er * si);

    float nr = w.x - 1.0f, ni = w.y;
    float den = arf * arf + aif * aif;
    float inv = 1.0f / den;
    float fr = (nr * arf + ni * aif) * inv;
    float fi = (ni * arf - nr * aif) * inv;
    float cr = Cr[idx], ci = Ci[idx];
    float2 C2 = make_float2(2.0f * (cr * fr - ci * fi),
                            2.0f * (cr * fi + ci * fr));

    g_aux[idx] = make_float4(dtar, dtai, C2.x, C2.y);

    // V chain: w^b, imag pre-negated, b-major
    {
        float2 v = make_float2(1.0f, 0.0f);
        float2* gv = g_V + h * (NH * NH) + n;
        #pragma unroll 4
        for (int b = 0; b < NH; ++b) {
            gv[b * NH] = make_float2(v.x, -v.y);
            v = cmulf(v, w);
        }
    }
    // TWr chain: (w^32)^r from accurate anchor
    {
        float2 W = bigpow(dtar, dtai, 32.0f);
        float2 x = make_float2(1.0f, 0.0f);
        float2* gt = g_TWr + h * (NH * NH) + n;
        #pragma unroll 4
        for (int r = 0; r < NH; ++r) {
            gt[r * NH] = x;
            x = cmulf(x, W);
        }
    }
}

// ---------------- Setup 2: Mq anchors (one bigpow per thread) ----------------
__global__ void __launch_bounds__(256) s4d_setup2() {
    int idx = blockIdx.x * 256 + threadIdx.x;       // h*256 + q*32 + n
    int h = idx >> 8;
    int q = (idx >> 5) & 7;
    int n = idx & 31;
    float4 a = g_aux[h * NH + n];
    float2 C2 = make_float2(a.z, a.w);
    float2 J  = bigpow(a.x, a.y, 1024.0f * (float)q);
    g_Mq[(h * 8 + q) * NH + n] = cmulf(C2, J);
}

// ---------------- Main: mma.sync bf16, 3-pass split ----------------
// Grid = HH*2 (h, half).  Block = 128 (4 warps).  Warp wid handles a-tiles
// T = 8*half + wid + 4*t', t' in {0,1} (16 rows each).
// B fragments staged in smem, frag-ordered: Bf[split][s][m][lane*2 + reg].
__global__ void __launch_bounds__(128) s4d_main(float* __restrict__ out) {
    __shared__ uint32_t Bf[2 * 4 * 4 * 64];     // 8 KB

    int h    = blockIdx.x >> 1;
    int half = blockIdx.x & 1;
    int tid  = threadIdx.x;
    int wid  = tid >> 5;
    int lane = tid & 31;
    int tig  = lane & 3;         // thread-in-group
    int g    = lane >> 2;        // group id

    // ---- build B fragment array (once per block) ----
    #pragma unroll
    for (int i = 0; i < 8; ++i) {
        int e  = tid + i * 128;          // 0..1023  (s, m, lane_t, reg)
        int s  = e >> 8;
        int m  = (e >> 6) & 3;
        int li = e & 63;
        int lt = li >> 1;
        int rg = li & 1;
        int n  = 8 * s + (lt & 3) + 4 * rg;
        int b  = 8 * m + (lt >> 2);
        float2 v = g_V[h * (NH * NH) + b * NH + n];   // (VR, -VI)
        uint32_t p0, p1;
        bfsplit(v.x, v.y, p0, p1);
        Bf[((0 * 4 + s) * 4 + m) * 64 + li] = p0;     // hi
        Bf[((1 * 4 + s) * 4 + m) * 64 + li] = p1;     // lo (residual)
    }
    __syncthreads();

    // ---- persist TWr for this lane's two rows x 8 modes ----
    // rows (a & 31): rl0 = 16*(T&1) + g, rl1 = rl0 + 8 ; T&1 == wid&1 (stride-4 tiles)
    int rl0 = ((wid & 1) << 4) + g;
    int rl1 = rl0 + 8;
    float2 tw0[8], tw1[8];
    #pragma unroll
    for (int j = 0; j < 8; ++j) {
        int n = tig + 4 * j;
        tw0[j] = g_TWr[h * (NH * NH) + rl0 * NH + n];
        tw1[j] = g_TWr[h * (NH * NH) + rl1 * NH + n];
    }

    #pragma unroll
    for (int tp = 0; tp < 2; ++tp) {
        int T = 8 * half + wid + 4 * tp;     // global a-tile (16 rows)
        int q = T >> 1;                      // a >> 5

        // ---- generate A fragments: A0/A1 [row 0/1][j], j = k-pair index ----
        uint32_t A0[2][8], A1[2][8];
        #pragma unroll
        for (int j = 0; j < 8; ++j) {
            int n = tig + 4 * j;
            float2 mq = g_Mq[(h * 8 + q) * NH + n];
            float re0 = fmaf(mq.x, tw0[j].x, -(mq.y * tw0[j].y));
            float im0 = fmaf(mq.x, tw0[j].y,  (mq.y * tw0[j].x));
            bfsplit(re0, im0, A0[0][j], A1[0][j]);
            float re1 = fmaf(mq.x, tw1[j].x, -(mq.y * tw1[j].y));
            float im1 = fmaf(mq.x, tw1[j].y,  (mq.y * tw1[j].x));
            bfsplit(re1, im1, A0[1][j], A1[1][j]);
        }

        float acc[4][4];
        #pragma unroll
        for (int m = 0; m < 4; ++m)
            #pragma unroll
            for (int k = 0; k < 4; ++k) acc[m][k] = 0.0f;

        // ---- 3 passes: A0*B1, A1*B0, A0*B0 ----
        #pragma unroll
        for (int p = 0; p < 3; ++p) {
            int bsplit = (p == 0) ? 1 : 0;
            #pragma unroll
            for (int s = 0; s < 4; ++s) {
                uint32_t a0 = (p == 1) ? A1[0][2 * s]     : A0[0][2 * s];
                uint32_t a1 = (p == 1) ? A1[1][2 * s]     : A0[1][2 * s];
                uint32_t a2 = (p == 1) ? A1[0][2 * s + 1] : A0[0][2 * s + 1];
                uint32_t a3 = (p == 1) ? A1[1][2 * s + 1] : A0[1][2 * s + 1];
                #pragma unroll
                for (int m = 0; m < 4; ++m) {
                    uint2 bb = *reinterpret_cast<const uint2*>(
                        &Bf[((bsplit * 4 + s) * 4 + m) * 64 + lane * 2]);
                    mma_bf16(acc[m][0], acc[m][1], acc[m][2], acc[m][3],
                             a0, a1, a2, a3, bb.x, bb.y);
                }
            }
        }

        // ---- store: c0,c1 -> row 16T+g ; c2,c3 -> row 16T+g+8 ; cols 8m+2*tig ----
        float* oph = out + h * LL;
        #pragma unroll
        for (int m = 0; m < 4; ++m) {
            int bc = 8 * m + 2 * tig;
            __stcs((float2*)(oph + (16 * T + g) * NH + bc),
                   make_float2(acc[m][0], acc[m][1]));
            __stcs((float2*)(oph + (16 * T + g + 8) * NH + bc),
                   make_float2(acc[m][2], acc[m][3]));
        }
    }
}

extern "C" void kernel_launch(void* const* d_in, const int* in_sizes, int n_in,
                              void* d_out, int out_size) {
    const float* C_real     = (const float*)d_in[0];
    const float* C_imag     = (const float*)d_in[1];
    const float* log_dt     = (const float*)d_in[2];
    const float* log_a_real = (const float*)d_in[3];
    const float* A_imag     = (const float*)d_in[4];
    float* out = (float*)d_out;

    s4d_setup1<<<HH / 8, 256>>>(C_real, C_imag, log_dt, log_a_real, A_imag);
    s4d_setup2<<<HH, 256>>>();
    s4d_main<<<HH * 2, 128>>>(out);
}